// round 5
// baseline (speedup 1.0000x reference)
#include <cuda_runtime.h>
#include <cuda_bf16.h>
#include <cstdint>

// ---------------------------------------------------------------------------
// OuterProductMean fused: S=256, N=256, c_m=256, c_h=32, c_z=128
//   k_lnproj : LN + dual projection -> bf16 hi/lo, K-major [m=8192][s=256]
//   k_wprep  : w_out fp32 [1024][128] -> bf16 hi/lo transposed [z=128][k=1024]
//   k_norm   : g_rnorm[i,j] = 1/(sum_s mask[s,i]mask[s,j] + 1e-3)
//   k_fused  : per 128x128 tile of C = A B^T (HMMA split-bf16, K=256), the tile
//              holds the FULL (c,e) space of 16 (i,j) pairs -> epilogue GEMM
//              (M=16 pairs, N=128 z, K=1024 ce) against W, writes out directly.
// All PTX sm_80-compatible (mma.sync/ldmatrix/cp.async) -> ok for compute_100.
// ---------------------------------------------------------------------------

#define S_DIM 256
#define N_DIM 256
#define CM    256
#define CH    32
#define CZ    128
#define NH    8192

__device__ __align__(16) __nv_bfloat16 g_Ah[(size_t)NH * S_DIM];
__device__ __align__(16) __nv_bfloat16 g_Al[(size_t)NH * S_DIM];
__device__ __align__(16) __nv_bfloat16 g_Bh[(size_t)NH * S_DIM];
__device__ __align__(16) __nv_bfloat16 g_Bl[(size_t)NH * S_DIM];
__device__ __align__(16) __nv_bfloat16 g_Wh[CZ * 1024];
__device__ __align__(16) __nv_bfloat16 g_Wl[CZ * 1024];
__device__ __align__(16) float g_rnorm[N_DIM * N_DIM];

// ---- PTX helpers -----------------------------------------------------------
__device__ __forceinline__ uint32_t smem_u32(const void* p) {
    uint32_t a;
    asm("{ .reg .u64 t; cvta.to.shared.u64 t, %1; cvt.u32.u64 %0, t; }" : "=r"(a) : "l"(p));
    return a;
}
__device__ __forceinline__ void cp16(uint32_t dst, const void* src) {
    asm volatile("cp.async.cg.shared.global [%0], [%1], 16;" :: "r"(dst), "l"(src));
}
#define CP_COMMIT() asm volatile("cp.async.commit_group;" ::: "memory")
#define CP_WAIT(n)  asm volatile("cp.async.wait_group %0;" :: "n"(n) : "memory")

__device__ __forceinline__ void ldm4(uint32_t* r, uint32_t addr) {
    asm volatile("ldmatrix.sync.aligned.m8n8.x4.shared.b16 {%0,%1,%2,%3}, [%4];"
                 : "=r"(r[0]), "=r"(r[1]), "=r"(r[2]), "=r"(r[3]) : "r"(addr));
}
__device__ __forceinline__ void mma_bf16(float* c, const uint32_t* a, const uint32_t* b) {
    asm volatile(
        "mma.sync.aligned.m16n8k16.row.col.f32.bf16.bf16.f32 "
        "{%0,%1,%2,%3}, {%4,%5,%6,%7}, {%8,%9}, {%0,%1,%2,%3};"
        : "+f"(c[0]), "+f"(c[1]), "+f"(c[2]), "+f"(c[3])
        : "r"(a[0]), "r"(a[1]), "r"(a[2]), "r"(a[3]), "r"(b[0]), "r"(b[1]));
}

// smem geometry
#define ROW_B   80                    // 32 bf16 + 16B pad (conflict-free)
#define ARR_SZ  (128 * ROW_B)         // 10240
#define STG_SZ  (4 * ARR_SZ)          // 40960 per main stage (Ah,Al,Bh,Bl)
#define OFF_0   0
#define OFF_1   ARR_SZ
#define OFF_2   (2 * ARR_SZ)
#define OFF_3   (3 * ARR_SZ)
// epilogue regions (reuse dead stage memory)
#define AP_STRIDE 2064                // 1024 bf16 + 16B pad
#define AP_SZ   (16 * AP_STRIDE)      // 33024 per array (hi, lo)
#define W_OFF   (2 * AP_SZ)           // 66048
#define W_ARR   (128 * ROW_B)         // 10240 per array
#define W_STG   (2 * W_ARR)           // 20480 per stage (hi, lo)
#define SMEM_TOTAL (W_OFF + 2 * W_STG)   // 107008

// ---------------------------------------------------------------------------
__global__ __launch_bounds__(256) void k_norm(const float* __restrict__ mask) {
    const int i = blockIdx.x;
    const int j = threadIdx.x;
    __shared__ float colI[S_DIM];
    colI[j] = mask[j * N_DIM + i];
    __syncthreads();
    float acc = 0.0f;
#pragma unroll 8
    for (int s = 0; s < S_DIM; s++) acc += colI[s] * mask[s * N_DIM + j];
    g_rnorm[i * N_DIM + j] = 1.0f / (acc + 1e-3f);
}

__global__ __launch_bounds__(256) void k_wprep(const float* __restrict__ wout) {
    const int z = blockIdx.x;
    for (int k = threadIdx.x; k < 1024; k += 256) {
        const float w = wout[(size_t)k * CZ + z];
        const __nv_bfloat16 h = __float2bfloat16(w);
        g_Wh[z * 1024 + k] = h;
        g_Wl[z * 1024 + k] = __float2bfloat16(w - __bfloat162float(h));
    }
}

// ---------------------------------------------------------------------------
// LN + dual projection -> transposed bf16 hi/lo (K-major).
// grid = (n=256, sg=8); 256 threads; 32 rows (same n, s = sg*32..+32).
// ---------------------------------------------------------------------------
__global__ __launch_bounds__(256) void k_lnproj(
    const float* __restrict__ m, const float* __restrict__ mask,
    const float* __restrict__ lnw, const float* __restrict__ lnb,
    const float* __restrict__ w1, const float* __restrict__ b1,
    const float* __restrict__ w2, const float* __restrict__ b2)
{
    const int tid  = threadIdx.x;
    const int c    = tid & 63;
    const int g    = tid >> 6;
    const int lane = tid & 31;
    const int wid  = tid >> 5;
    const int n    = blockIdx.x;
    const int sg   = blockIdx.y;

    float wreg[64];
#pragma unroll
    for (int kk = 0; kk < 64; kk++) {
        const int k = g * 64 + kk;
        wreg[kk] = (c < CH) ? w1[k * CH + c] : w2[k * CH + (c - CH)];
    }
    const float bias = (c < CH) ? b1[c] : b2[c - CH];
    const float wln = lnw[tid];
    const float bln = lnb[tid];

    __shared__ float ysm[CM];
    __shared__ float red1[8], red2[8];
    __shared__ float psum[4][64];
    __shared__ float aout[32][33];
    __shared__ float bout_s[32][33];

    for (int r = 0; r < 32; r++) {
        const int row = (sg * 32 + r) * N_DIM + n;
        const float x = m[(size_t)row * CM + tid];

        float s1 = x, s2 = x * x;
#pragma unroll
        for (int off = 16; off; off >>= 1) {
            s1 += __shfl_xor_sync(0xffffffffu, s1, off);
            s2 += __shfl_xor_sync(0xffffffffu, s2, off);
        }
        if (lane == 0) { red1[wid] = s1; red2[wid] = s2; }
        __syncthreads();

        float t1 = 0.f, t2 = 0.f;
#pragma unroll
        for (int w = 0; w < 8; w++) { t1 += red1[w]; t2 += red2[w]; }
        const float mean = t1 * (1.0f / CM);
        const float var  = t2 * (1.0f / CM) - mean * mean;
        const float inv  = rsqrtf(var + 1e-5f);
        ysm[tid] = (x - mean) * inv * wln + bln;
        __syncthreads();

        float p = 0.f;
#pragma unroll
        for (int kk = 0; kk < 64; kk++) p += ysm[g * 64 + kk] * wreg[kk];
        psum[g][c] = p;
        __syncthreads();

        if (tid < 64) {
            const float tot = psum[0][tid] + psum[1][tid] + psum[2][tid] + psum[3][tid];
            const float v = (tot + bias) * mask[row];
            if (tid < CH) aout[r][tid]        = v;
            else          bout_s[r][tid - CH] = v;
        }
        __syncthreads();
    }

    for (int idx = tid; idx < 1024; idx += 256) {
        const int cc = idx >> 5;
        const int sl = idx & 31;
        const size_t mrow = (size_t)(n * CH + cc) * S_DIM + sg * 32 + sl;

        const float va = aout[sl][cc];
        const __nv_bfloat16 ah = __float2bfloat16(va);
        g_Ah[mrow] = ah;
        g_Al[mrow] = __float2bfloat16(va - __bfloat162float(ah));

        const float vb = bout_s[sl][cc];
        const __nv_bfloat16 bh = __float2bfloat16(vb);
        g_Bh[mrow] = bh;
        g_Bl[mrow] = __float2bfloat16(vb - __bfloat162float(bh));
    }
}

// ---------------------------------------------------------------------------
// Fused GEMM1 + GEMM2. 8 warps as 4(m) x 2(n); warp tile 32(m) x 64(n).
// ---------------------------------------------------------------------------
__global__ __launch_bounds__(256, 2) void k_fused(
    const float* __restrict__ bout, float* __restrict__ out)
{
    extern __shared__ char smraw[];
    const uint32_t sm0 = smem_u32(smraw);
    const int tid  = threadIdx.x;
    const int wid  = tid >> 5;
    const int lane = tid & 31;
    const int m0 = blockIdx.y * 128;
    const int n0 = blockIdx.x * 128;
    const int wm0 = (wid & 3) * 32;
    const int wn0 = (wid >> 2) * 64;

    // ldmatrix lane patterns (A: m16k16 row-major; B: n-rows K-major)
    const int ar = lane & 15;
    const int ak = (lane >> 4) * 16;
    const int br = (lane & 7) + ((lane >> 4) << 3);
    const int bk = ((lane >> 3) & 1) * 16;
    const uint32_t aoff = (uint32_t)(wm0 + ar) * ROW_B + ak;
    const uint32_t boff = (uint32_t)(wn0 + br) * ROW_B + bk;

    float acc[2][8][4];
#pragma unroll
    for (int t = 0; t < 2; t++)
#pragma unroll
        for (int j = 0; j < 8; j++)
#pragma unroll
            for (int q = 0; q < 4; q++) acc[t][j][q] = 0.f;

    auto stage = [&](int kc, uint32_t sbuf) {
#pragma unroll
        for (int l = 0; l < 2; l++) {
            const int idx = tid + 256 * l;
            const int row = idx >> 2;
            const int seg = idx & 3;
            const uint32_t d = sbuf + row * ROW_B + seg * 16;
            const size_t sa = (size_t)(m0 + row) * S_DIM + kc * 32 + seg * 8;
            const size_t sb = (size_t)(n0 + row) * S_DIM + kc * 32 + seg * 8;
            cp16(d + OFF_0, g_Ah + sa);
            cp16(d + OFF_1, g_Al + sa);
            cp16(d + OFF_2, g_Bh + sb);
            cp16(d + OFF_3, g_Bl + sb);
        }
        CP_COMMIT();
    };

    stage(0, sm0);
    stage(1, sm0 + STG_SZ);

    for (int kc = 0; kc < 8; kc++) {
        if (kc < 7) { CP_WAIT(1); } else { CP_WAIT(0); }
        __syncthreads();
        const uint32_t sbuf = sm0 + (kc & 1) * STG_SZ;
#pragma unroll
        for (int ks = 0; ks < 2; ks++) {
            uint32_t aH[2][4], aL[2][4], bH[4][4], bL[4][4];
#pragma unroll
            for (int t = 0; t < 2; t++) {
                const uint32_t a = sbuf + aoff + t * (16 * ROW_B) + ks * 32;
                ldm4(aH[t], a + OFF_0);
                ldm4(aL[t], a + OFF_1);
            }
#pragma unroll
            for (int p = 0; p < 4; p++) {
                const uint32_t b = sbuf + boff + p * (16 * ROW_B) + ks * 32;
                ldm4(bH[p], b + OFF_2);
                ldm4(bL[p], b + OFF_3);
            }
#pragma unroll
            for (int t = 0; t < 2; t++) {
#pragma unroll
                for (int j = 0; j < 8; j++) {
                    const uint32_t* bh = &bH[j >> 1][(j & 1) * 2];
                    const uint32_t* bl = &bL[j >> 1][(j & 1) * 2];
                    mma_bf16(acc[t][j], aH[t], bh);
                    mma_bf16(acc[t][j], aH[t], bl);
                    mma_bf16(acc[t][j], aL[t], bh);
                }
            }
        }
        __syncthreads();
        if (kc + 2 < 8) stage(kc + 2, sbuf);
    }
    // stages now dead; all cp groups drained (CP_WAIT(0) at kc=7)

    // ---- prefetch W chunks 0,1 (region [W_OFF, +2*W_STG), disjoint from AP)
    auto stageW = [&](int wc, uint32_t wbuf) {
#pragma unroll
        for (int l = 0; l < 2; l++) {
            const int idx = tid + 256 * l;
            const int row = idx >> 2;              // z
            const int seg = idx & 3;
            const uint32_t d = wbuf + row * ROW_B + seg * 16;
            const size_t s = (size_t)row * 1024 + wc * 32 + seg * 8;
            cp16(d, g_Wh + s);
            cp16(d + W_ARR, g_Wl + s);
        }
        CP_COMMIT();
    };
    stageW(0, sm0 + W_OFF);
    stageW(1, sm0 + W_OFF + W_STG);

    // ---- spill C tile to smem as Apair[16 pairs][1024 ce] bf16 hi/lo
#pragma unroll
    for (int t = 0; t < 2; t++) {
#pragma unroll
        for (int j = 0; j < 8; j++) {
#pragma unroll
            for (int h = 0; h < 2; h++) {
                const int mm = wm0 + t * 16 + (lane >> 2) + h * 8;
                const int nn = wn0 + j * 8 + (lane & 3) * 2;
                const int p  = ((mm >> 5) << 2) + (nn >> 5);
                const int ce = (mm & 31) * 32 + (nn & 31);
                const float v0 = acc[t][j][h * 2 + 0];
                const float v1 = acc[t][j][h * 2 + 1];
                const __nv_bfloat16 h0 = __float2bfloat16(v0);
                const __nv_bfloat16 h1 = __float2bfloat16(v1);
                __nv_bfloat162 hp; hp.x = h0; hp.y = h1;
                __nv_bfloat162 lp;
                lp.x = __float2bfloat16(v0 - __bfloat162float(h0));
                lp.y = __float2bfloat16(v1 - __bfloat162float(h1));
                const uint32_t o = (uint32_t)p * AP_STRIDE + ce * 2;
                *(uint32_t*)(smraw + o)         = *(uint32_t*)&hp;
                *(uint32_t*)(smraw + AP_SZ + o) = *(uint32_t*)&lp;
            }
        }
    }

    // ---- epilogue GEMM: out_pair[16, z=128] = Apair[16,1024] @ W[1024,128]
    // per warp: 16 z (2 n-tiles), M=16, K=1024 in 32 chunks of 32.
    const int z0 = wid * 16;
    const uint32_t apA  = sm0 + (uint32_t)ar * AP_STRIDE + ak;   // + AP hi
    const uint32_t boffw = (uint32_t)(z0 + br) * ROW_B + bk;

    float acc2[2][4];
#pragma unroll
    for (int nt = 0; nt < 2; nt++)
#pragma unroll
        for (int q = 0; q < 4; q++) acc2[nt][q] = 0.f;

    for (int wc = 0; wc < 32; wc++) {
        if (wc < 31) { CP_WAIT(1); } else { CP_WAIT(0); }
        __syncthreads();
        const uint32_t wbuf = sm0 + W_OFF + (wc & 1) * W_STG;
#pragma unroll
        for (int ks = 0; ks < 2; ks++) {
            uint32_t aH[4], aL[4], bH[4], bL[4];
            const uint32_t a = apA + wc * 64 + ks * 32;
            ldm4(aH, a);
            ldm4(aL, a + AP_SZ);
            const uint32_t b = wbuf + boffw + ks * 32;
            ldm4(bH, b);
            ldm4(bL, b + W_ARR);
#pragma unroll
            for (int nt = 0; nt < 2; nt++) {
                mma_bf16(acc2[nt], aH, &bH[nt * 2]);
                mma_bf16(acc2[nt], aH, &bL[nt * 2]);
                mma_bf16(acc2[nt], aL, &bH[nt * 2]);
            }
        }
        __syncthreads();
        if (wc + 2 < 32) stageW(wc + 2, wbuf);
    }

    // ---- store: out[(i,j),z] = (acc + bias) * rnorm
    const int i0 = blockIdx.y * 4;
    const int j0 = blockIdx.x * 4;
    const int qc = (lane & 3) * 2;
#pragma unroll
    for (int h = 0; h < 2; h++) {
        const int p = (lane >> 2) + h * 8;
        const int ij = (i0 + (p >> 2)) * N_DIM + j0 + (p & 3);
        const float rn = g_rnorm[ij];
        float* ob = out + (size_t)ij * CZ;
#pragma unroll
        for (int nt = 0; nt < 2; nt++) {
            const int z = z0 + nt * 8 + qc;
            const float2 bz = *(const float2*)(bout + z);
            float2 o;
            o.x = (acc2[nt][h * 2 + 0] + bz.x) * rn;
            o.y = (acc2[nt][h * 2 + 1] + bz.y) * rn;
            *(float2*)(ob + z) = o;
        }
    }
}

// ---------------------------------------------------------------------------
extern "C" void kernel_launch(void* const* d_in, const int* in_sizes, int n_in,
                              void* d_out, int out_size)
{
    (void)in_sizes; (void)n_in; (void)out_size;
    const float* m    = (const float*)d_in[0];
    const float* mask = (const float*)d_in[1];
    const float* lnw  = (const float*)d_in[2];
    const float* lnb  = (const float*)d_in[3];
    const float* w1   = (const float*)d_in[4];
    const float* b1   = (const float*)d_in[5];
    const float* w2   = (const float*)d_in[6];
    const float* b2   = (const float*)d_in[7];
    const float* wout = (const float*)d_in[8];
    const float* bout = (const float*)d_in[9];
    float* out = (float*)d_out;

    cudaFuncSetAttribute((const void*)k_fused,
                         cudaFuncAttributeMaxDynamicSharedMemorySize, SMEM_TOTAL);

    k_lnproj<<<dim3(N_DIM, 8), 256>>>(m, mask, lnw, lnb, w1, b1, w2, b2);
    k_wprep<<<CZ, 256>>>(wout);
    k_norm<<<N_DIM, 256>>>(mask);
    k_fused<<<dim3(64, 64), 256, SMEM_TOTAL>>>(bout, out);
}

// round 8
// speedup vs baseline: 1.4325x; 1.4325x over previous
#include <cuda_runtime.h>
#include <cuda_bf16.h>
#include <cstdint>

// ---------------------------------------------------------------------------
// OuterProductMean: S=256, N=256, c_m=256, c_h=32, c_z=128
//   k_lnproj : LN + dual projection -> bf16 hi/lo, K-major [m=8192][s=256]
//   k_wprep  : w_out fp32 [1024][128] -> bf16 hi/lo transposed [z=128][k=1024]
//   k_norm   : g_rnorm[i,j] = 1/(sum_s mask[s,i]mask[s,j] + 1e-3)
//   k_gemm1  : HMMA split-bf16  C[8192x8192] = A B^T (K=256), C stored bf16 hi/lo
//   k_gemm2  : HMMA split-bf16  out[(i,j),z]; K-chunks are contiguous C rows.
// All PTX sm_80-compatible (mma.sync/ldmatrix/cp.async) -> ok for compute_100.
// ---------------------------------------------------------------------------

#define S_DIM 256
#define N_DIM 256
#define CM    256
#define CH    32
#define CZ    128
#define NH    8192

__device__ __align__(16) __nv_bfloat16 g_Ah[(size_t)NH * S_DIM];
__device__ __align__(16) __nv_bfloat16 g_Al[(size_t)NH * S_DIM];
__device__ __align__(16) __nv_bfloat16 g_Bh[(size_t)NH * S_DIM];
__device__ __align__(16) __nv_bfloat16 g_Bl[(size_t)NH * S_DIM];
__device__ __align__(16) __nv_bfloat16 g_Ch[(size_t)NH * NH];   // 134 MB
__device__ __align__(16) __nv_bfloat16 g_Cl[(size_t)NH * NH];   // 134 MB
__device__ __align__(16) __nv_bfloat16 g_Wh[CZ * 1024];
__device__ __align__(16) __nv_bfloat16 g_Wl[CZ * 1024];
__device__ __align__(16) float g_rnorm[N_DIM * N_DIM];

// ---- PTX helpers -----------------------------------------------------------
__device__ __forceinline__ uint32_t smem_u32(const void* p) {
    uint32_t a;
    asm("{ .reg .u64 t; cvta.to.shared.u64 t, %1; cvt.u32.u64 %0, t; }" : "=r"(a) : "l"(p));
    return a;
}
__device__ __forceinline__ void cp16(uint32_t dst, const void* src) {
    asm volatile("cp.async.cg.shared.global [%0], [%1], 16;" :: "r"(dst), "l"(src));
}
#define CP_COMMIT() asm volatile("cp.async.commit_group;" ::: "memory")
#define CP_WAIT(n)  asm volatile("cp.async.wait_group %0;" :: "n"(n) : "memory")

__device__ __forceinline__ void ldm4(uint32_t* r, uint32_t addr) {
    asm volatile("ldmatrix.sync.aligned.m8n8.x4.shared.b16 {%0,%1,%2,%3}, [%4];"
                 : "=r"(r[0]), "=r"(r[1]), "=r"(r[2]), "=r"(r[3]) : "r"(addr));
}
__device__ __forceinline__ void mma_bf16(float* c, const uint32_t* a, const uint32_t* b) {
    asm volatile(
        "mma.sync.aligned.m16n8k16.row.col.f32.bf16.bf16.f32 "
        "{%0,%1,%2,%3}, {%4,%5,%6,%7}, {%8,%9}, {%0,%1,%2,%3};"
        : "+f"(c[0]), "+f"(c[1]), "+f"(c[2]), "+f"(c[3])
        : "r"(a[0]), "r"(a[1]), "r"(a[2]), "r"(a[3]), "r"(b[0]), "r"(b[1]));
}

// smem tile geometry (both GEMMs): 128 rows x 32 bf16, stride 80 B
#define ROW_B   80
#define ARR_SZ  (128 * ROW_B)        // 10240
#define STG_SZ  (4 * ARR_SZ)         // 40960 per stage
#define OFF_0   0
#define OFF_1   ARR_SZ
#define OFF_2   (2 * ARR_SZ)
#define OFF_3   (3 * ARR_SZ)
#define SMEM_GEMM (2 * STG_SZ)       // 81920

// ---------------------------------------------------------------------------
__global__ __launch_bounds__(256) void k_norm(const float* __restrict__ mask) {
    const int i = blockIdx.x;
    const int j = threadIdx.x;
    __shared__ float colI[S_DIM];
    colI[j] = mask[j * N_DIM + i];
    __syncthreads();
    float acc = 0.0f;
#pragma unroll 8
    for (int s = 0; s < S_DIM; s++) acc += colI[s] * mask[s * N_DIM + j];
    g_rnorm[i * N_DIM + j] = 1.0f / (acc + 1e-3f);
}

__global__ __launch_bounds__(256) void k_wprep(const float* __restrict__ wout) {
    const int z = blockIdx.x;
    for (int k = threadIdx.x; k < 1024; k += 256) {
        const float w = wout[(size_t)k * CZ + z];
        const __nv_bfloat16 h = __float2bfloat16(w);
        g_Wh[z * 1024 + k] = h;
        g_Wl[z * 1024 + k] = __float2bfloat16(w - __bfloat162float(h));
    }
}

// ---------------------------------------------------------------------------
// LN + dual projection, batched phases; psum overlays dead xs region (32 KB).
// grid = (n=256, sg=8); 256 threads; rows s = sg*32..+32 at fixed n.
// ---------------------------------------------------------------------------
__global__ __launch_bounds__(256) void k_lnproj(
    const float* __restrict__ m, const float* __restrict__ mask,
    const float* __restrict__ lnw, const float* __restrict__ lnb,
    const float* __restrict__ w1, const float* __restrict__ b1,
    const float* __restrict__ w2, const float* __restrict__ b2)
{
    const int tid  = threadIdx.x;
    const int lane = tid & 31;
    const int wid  = tid >> 5;
    const int n    = blockIdx.x;
    const int sg   = blockIdx.y;

    __shared__ float xs[32 * 256];          // phase A-D: rows; phase E: psum
    __shared__ float mu_s[32], inv_s[32];

    // thread projection identity: c = tid&63 (c<32: w1, else w2), g = tid>>6
    const int c = tid & 63;
    const int g = tid >> 6;
    float4 wreg[16];
#pragma unroll
    for (int k4 = 0; k4 < 16; k4++) {
        const int k = g * 64 + k4 * 4;
        if (c < CH) {
            wreg[k4] = make_float4(w1[k * CH + c], w1[(k + 1) * CH + c],
                                   w1[(k + 2) * CH + c], w1[(k + 3) * CH + c]);
        } else {
            const int cc = c - CH;
            wreg[k4] = make_float4(w2[k * CH + cc], w2[(k + 1) * CH + cc],
                                   w2[(k + 2) * CH + cc], w2[(k + 3) * CH + cc]);
        }
    }
    const float wln = lnw[tid];
    const float bln = lnb[tid];

    // Phase A: load 32 rows (coalesced float4)
#pragma unroll
    for (int l = 0; l < 8; l++) {
        const int idx = tid + 256 * l;          // 2048 float4
        const int r   = idx >> 6;
        const int c4  = idx & 63;
        const size_t row = (size_t)((sg * 32 + r) * N_DIM + n);
        ((float4*)xs)[r * 64 + c4] = ((const float4*)(m + row * CM))[c4];
    }
    __syncthreads();

    // Phase B: stats, warp w handles rows 4w..4w+3
#pragma unroll
    for (int rr = 0; rr < 4; rr++) {
        const int r = wid * 4 + rr;
        float s1 = 0.f, s2 = 0.f;
#pragma unroll
        for (int q = 0; q < 8; q++) {
            const float x = xs[r * 256 + lane + 32 * q];
            s1 += x; s2 += x * x;
        }
#pragma unroll
        for (int off = 16; off; off >>= 1) {
            s1 += __shfl_xor_sync(0xffffffffu, s1, off);
            s2 += __shfl_xor_sync(0xffffffffu, s2, off);
        }
        if (lane == 0) {
            const float mean = s1 * (1.0f / CM);
            const float var  = s2 * (1.0f / CM) - mean * mean;
            mu_s[r]  = mean;
            inv_s[r] = rsqrtf(var + 1e-5f);
        }
    }
    __syncthreads();

    // Phase C: normalize column tid across all rows (in place)
#pragma unroll 4
    for (int r = 0; r < 32; r++) {
        const float x = xs[r * 256 + tid];
        xs[r * 256 + tid] = (x - mu_s[r]) * inv_s[r] * wln + bln;
    }
    __syncthreads();

    // Phase D: projection partials kept in registers (pr[r] for this (g,c))
    float pr[32];
#pragma unroll 2
    for (int r = 0; r < 32; r++) {
        const float4* yp = (const float4*)&xs[r * 256 + g * 64];
        float p = 0.f;
#pragma unroll
        for (int k4 = 0; k4 < 16; k4++) {
            const float4 y = yp[k4];
            const float4 w = wreg[k4];
            p += y.x * w.x + y.y * w.y + y.z * w.z + y.w * w.w;
        }
        pr[r] = p;
    }
    __syncthreads();     // xs reads done -> safe to overwrite with psum

    // write psum[(g*64+c)*32 + r], staggered by lane to avoid bank conflicts
#pragma unroll
    for (int rr = 0; rr < 32; rr++) {
        const int r = (lane + rr) & 31;
        xs[(g * 64 + c) * 32 + r] = pr[r];
    }
    __syncthreads();

    // Phase E: reduce over g, bias, mask, split hi/lo, store
    const int r = tid & 31;
    const size_t row = (size_t)((sg * 32 + r) * N_DIM + n);
    const float msk = mask[row];
#pragma unroll
    for (int l = 0; l < 8; l++) {
        const int cc = (tid >> 5) + 8 * l;      // 0..63
        const float tot = xs[(0 * 64 + cc) * 32 + r] + xs[(1 * 64 + cc) * 32 + r] +
                          xs[(2 * 64 + cc) * 32 + r] + xs[(3 * 64 + cc) * 32 + r];
        const float bias = (cc < CH) ? b1[cc] : b2[cc - CH];
        const float v = (tot + bias) * msk;
        const __nv_bfloat16 h = __float2bfloat16(v);
        const __nv_bfloat16 lo = __float2bfloat16(v - __bfloat162float(h));
        if (cc < CH) {
            const size_t mrow = (size_t)(n * CH + cc) * S_DIM + sg * 32 + r;
            g_Ah[mrow] = h;  g_Al[mrow] = lo;
        } else {
            const size_t mrow = (size_t)(n * CH + (cc - CH)) * S_DIM + sg * 32 + r;
            g_Bh[mrow] = h;  g_Bl[mrow] = lo;
        }
    }
}

// ---------------------------------------------------------------------------
// Shared warp-tile compute: 8 warps as 4(m) x 2(n); warp tile 32(m) x 64(n).
// 32-wide K chunk, 3 split passes: XhYh + XhYl + XlYh.
// ---------------------------------------------------------------------------
__device__ __forceinline__ void compute_chunk(
    uint32_t sbuf, uint32_t aoff, uint32_t boff, float acc[2][8][4])
{
#pragma unroll
    for (int ks = 0; ks < 2; ks++) {
        uint32_t aH[2][4], aL[2][4], bH[4][4], bL[4][4];
#pragma unroll
        for (int t = 0; t < 2; t++) {
            const uint32_t a = sbuf + aoff + t * (16 * ROW_B) + ks * 32;
            ldm4(aH[t], a + OFF_0);
            ldm4(aL[t], a + OFF_1);
        }
#pragma unroll
        for (int p = 0; p < 4; p++) {
            const uint32_t b = sbuf + boff + p * (16 * ROW_B) + ks * 32;
            ldm4(bH[p], b + OFF_2);
            ldm4(bL[p], b + OFF_3);
        }
#pragma unroll
        for (int t = 0; t < 2; t++) {
#pragma unroll
            for (int j = 0; j < 8; j++) {
                const uint32_t* bh = &bH[j >> 1][(j & 1) * 2];
                const uint32_t* bl = &bL[j >> 1][(j & 1) * 2];
                mma_bf16(acc[t][j], aH[t], bh);
                mma_bf16(acc[t][j], aH[t], bl);
                mma_bf16(acc[t][j], aL[t], bh);
            }
        }
    }
}

// ---------------------------------------------------------------------------
// K2: C = A B^T. CTA tile 128x128, K=256 in 8 chunks, 2 CTAs/SM.
// ---------------------------------------------------------------------------
__global__ __launch_bounds__(256, 2) void k_gemm1() {
    extern __shared__ char smraw[];
    const uint32_t sm0 = smem_u32(smraw);
    const int tid  = threadIdx.x;
    const int wid  = tid >> 5;
    const int lane = tid & 31;
    const int m0 = blockIdx.y * 128;
    const int n0 = blockIdx.x * 128;
    const int wm0 = (wid & 3) * 32;
    const int wn0 = (wid >> 2) * 64;

    const int ar = lane & 15;
    const int ak = (lane >> 4) * 16;
    const int br = (lane & 7) + ((lane >> 4) << 3);
    const int bk = ((lane >> 3) & 1) * 16;
    const uint32_t aoff = (uint32_t)(wm0 + ar) * ROW_B + ak;
    const uint32_t boff = (uint32_t)(wn0 + br) * ROW_B + bk;

    float acc[2][8][4];
#pragma unroll
    for (int t = 0; t < 2; t++)
#pragma unroll
        for (int j = 0; j < 8; j++)
#pragma unroll
            for (int q = 0; q < 4; q++) acc[t][j][q] = 0.f;

    auto stage = [&](int kc, uint32_t sbuf) {
#pragma unroll
        for (int l = 0; l < 2; l++) {
            const int idx = tid + 256 * l;
            const int row = idx >> 2;
            const int seg = idx & 3;
            const uint32_t d = sbuf + row * ROW_B + seg * 16;
            const size_t sa = (size_t)(m0 + row) * S_DIM + kc * 32 + seg * 8;
            const size_t sb = (size_t)(n0 + row) * S_DIM + kc * 32 + seg * 8;
            cp16(d + OFF_0, g_Ah + sa);
            cp16(d + OFF_1, g_Al + sa);
            cp16(d + OFF_2, g_Bh + sb);
            cp16(d + OFF_3, g_Bl + sb);
        }
        CP_COMMIT();
    };

    stage(0, sm0);
    stage(1, sm0 + STG_SZ);

    for (int kc = 0; kc < 8; kc++) {
        if (kc < 7) { CP_WAIT(1); } else { CP_WAIT(0); }
        __syncthreads();
        const uint32_t sbuf = sm0 + (kc & 1) * STG_SZ;
        compute_chunk(sbuf, aoff, boff, acc);
        __syncthreads();
        if (kc + 2 < 8) stage(kc + 2, sbuf);
    }

    // epilogue: bf16 hi/lo split, packed u32 stores (row-major C)
#pragma unroll
    for (int t = 0; t < 2; t++) {
        const int mg = m0 + wm0 + t * 16 + (lane >> 2);
#pragma unroll
        for (int j = 0; j < 8; j++) {
            const int nn = n0 + wn0 + j * 8 + (lane & 3) * 2;
            const float* cc = acc[t][j];
#pragma unroll
            for (int h = 0; h < 2; h++) {
                const float v0 = cc[h * 2 + 0], v1 = cc[h * 2 + 1];
                const __nv_bfloat16 h0 = __float2bfloat16(v0);
                const __nv_bfloat16 h1 = __float2bfloat16(v1);
                __nv_bfloat162 hp; hp.x = h0; hp.y = h1;
                __nv_bfloat162 lp;
                lp.x = __float2bfloat16(v0 - __bfloat162float(h0));
                lp.y = __float2bfloat16(v1 - __bfloat162float(h1));
                const size_t o = (size_t)(mg + h * 8) * NH + nn;
                *(uint32_t*)(g_Ch + o) = *(uint32_t*)&hp;
                *(uint32_t*)(g_Cl + o) = *(uint32_t*)&lp;
            }
        }
    }
}

// ---------------------------------------------------------------------------
// K3: out[(i,j),z] = (sum_ce C[(i,c),(j,e)] W[ce,z] + b[z]) * rnorm[i,j]
// grid = 512: i = bx>>1, j-half = bx&1. CTA tile 128(j) x 128(z), K=1024 in
// 32 chunks; chunk c loads ONE contiguous half-row of C (8 KB hi + 8 KB lo).
// ---------------------------------------------------------------------------
__global__ __launch_bounds__(256, 2) void k_gemm2(
    const float* __restrict__ bout, float* __restrict__ out)
{
    extern __shared__ char smraw[];
    const uint32_t sm0 = smem_u32(smraw);
    const int tid  = threadIdx.x;
    const int wid  = tid >> 5;
    const int lane = tid & 31;
    const int i  = blockIdx.x >> 1;
    const int jh = blockIdx.x & 1;
    const int wm0 = (wid & 3) * 32;      // j within tile
    const int wn0 = (wid >> 2) * 64;     // z

    const int ar = lane & 15;
    const int ak = (lane >> 4) * 16;
    const int br = (lane & 7) + ((lane >> 4) << 3);
    const int bk = ((lane >> 3) & 1) * 16;
    const uint32_t aoff = (uint32_t)(wm0 + ar) * ROW_B + ak;
    const uint32_t boff = (uint32_t)(wn0 + br) * ROW_B + bk;

    float acc[2][8][4];
#pragma unroll
    for (int t = 0; t < 2; t++)
#pragma unroll
        for (int j = 0; j < 8; j++)
#pragma unroll
            for (int q = 0; q < 4; q++) acc[t][j][q] = 0.f;

    auto stage = [&](int kc, uint32_t sbuf) {
#pragma unroll
        for (int l = 0; l < 2; l++) {
            const int idx = tid + 256 * l;
            const int row = idx >> 2;            // j-row (C) / z-row (W)
            const int seg = idx & 3;
            const uint32_t d = sbuf + row * ROW_B + seg * 16;
            const size_t sc = (size_t)(i * 32 + kc) * NH + (jh * 128 + row) * 32 + seg * 8;
            const size_t sw = (size_t)row * 1024 + kc * 32 + seg * 8;
            cp16(d + OFF_0, g_Ch + sc);
            cp16(d + OFF_1, g_Cl + sc);
            cp16(d + OFF_2, g_Wh + sw);
            cp16(d + OFF_3, g_Wl + sw);
        }
        CP_COMMIT();
    };

    stage(0, sm0);
    stage(1, sm0 + STG_SZ);

    for (int kc = 0; kc < 32; kc++) {
        if (kc < 31) { CP_WAIT(1); } else { CP_WAIT(0); }
        __syncthreads();
        const uint32_t sbuf = sm0 + (kc & 1) * STG_SZ;
        compute_chunk(sbuf, aoff, boff, acc);
        __syncthreads();
        if (kc + 2 < 32) stage(kc + 2, sbuf);
    }

    // epilogue: + bias, * rnorm, fp32 stores
#pragma unroll
    for (int t = 0; t < 2; t++) {
        const int jg = jh * 128 + wm0 + t * 16 + (lane >> 2);
        const float rn0 = g_rnorm[i * N_DIM + jg];
        const float rn1 = g_rnorm[i * N_DIM + jg + 8];
#pragma unroll
        for (int j = 0; j < 8; j++) {
            const int z = wn0 + j * 8 + (lane & 3) * 2;
            const float2 bz = *(const float2*)(bout + z);
            const float* cc = acc[t][j];
            float2 o0, o1;
            o0.x = (cc[0] + bz.x) * rn0;  o0.y = (cc[1] + bz.y) * rn0;
            o1.x = (cc[2] + bz.x) * rn1;  o1.y = (cc[3] + bz.y) * rn1;
            *(float2*)(out + (size_t)(i * N_DIM + jg) * CZ + z)     = o0;
            *(float2*)(out + (size_t)(i * N_DIM + jg + 8) * CZ + z) = o1;
        }
    }
}

// ---------------------------------------------------------------------------
extern "C" void kernel_launch(void* const* d_in, const int* in_sizes, int n_in,
                              void* d_out, int out_size)
{
    (void)in_sizes; (void)n_in; (void)out_size;
    const float* m    = (const float*)d_in[0];
    const float* mask = (const float*)d_in[1];
    const float* lnw  = (const float*)d_in[2];
    const float* lnb  = (const float*)d_in[3];
    const float* w1   = (const float*)d_in[4];
    const float* b1   = (const float*)d_in[5];
    const float* w2   = (const float*)d_in[6];
    const float* b2   = (const float*)d_in[7];
    const float* wout = (const float*)d_in[8];
    const float* bout = (const float*)d_in[9];
    float* out = (float*)d_out;

    cudaFuncSetAttribute((const void*)k_gemm1,
                         cudaFuncAttributeMaxDynamicSharedMemorySize, SMEM_GEMM);
    cudaFuncSetAttribute((const void*)k_gemm2,
                         cudaFuncAttributeMaxDynamicSharedMemorySize, SMEM_GEMM);

    k_lnproj<<<dim3(N_DIM, 8), 256>>>(m, mask, lnw, lnb, w1, b1, w2, b2);
    k_wprep<<<CZ, 256>>>(wout);
    k_norm<<<N_DIM, 256>>>(mask);
    k_gemm1<<<dim3(NH / 128, NH / 128), 256, SMEM_GEMM>>>();
    k_gemm2<<<512, 256, SMEM_GEMM>>>(bout, out);
}

// round 10
// speedup vs baseline: 2.0635x; 1.4405x over previous
#include <cuda_runtime.h>
#include <cuda_fp16.h>
#include <cstdint>

// ---------------------------------------------------------------------------
// OuterProductMean: S=256, N=256, c_m=256, c_h=32, c_z=128
//   k_lnproj : LN + dual projection -> A as fp16 hi/lo, B as plain fp16,
//              K-major [m=8192][s=256]
//   k_wprep  : w_out fp32 [1024][128] -> fp16 hi/lo transposed [z=128][k=1024]
//   k_norm   : g_rnorm[i,j] = 1/(sum_s mask[s,i]mask[s,j] + 1e-3)
//   k_gemm1  : HMMA 2-pass  C[8192x8192] = (Ah+Al) B^T (K=256), C plain fp16
//   k_gemm2  : HMMA 2-pass  out = C (Wh+Wl) + bias, * rnorm
// All PTX sm_80-compatible (mma.sync/ldmatrix/cp.async) -> ok for compute_100.
// ---------------------------------------------------------------------------

#define S_DIM 256
#define N_DIM 256
#define CM    256
#define CH    32
#define CZ    128
#define NH    8192

__device__ __align__(16) __half g_Ah[(size_t)NH * S_DIM];
__device__ __align__(16) __half g_Al[(size_t)NH * S_DIM];
__device__ __align__(16) __half g_B [(size_t)NH * S_DIM];
__device__ __align__(16) __half g_C [(size_t)NH * NH];     // 134 MB
__device__ __align__(16) __half g_Wh[CZ * 1024];
__device__ __align__(16) __half g_Wl[CZ * 1024];
__device__ __align__(16) float g_rnorm[N_DIM * N_DIM];

// ---- PTX helpers -----------------------------------------------------------
__device__ __forceinline__ uint32_t smem_u32(const void* p) {
    uint32_t a;
    asm("{ .reg .u64 t; cvta.to.shared.u64 t, %1; cvt.u32.u64 %0, t; }" : "=r"(a) : "l"(p));
    return a;
}
__device__ __forceinline__ void cp16(uint32_t dst, const void* src) {
    asm volatile("cp.async.cg.shared.global [%0], [%1], 16;" :: "r"(dst), "l"(src));
}
#define CP_COMMIT() asm volatile("cp.async.commit_group;" ::: "memory")
#define CP_WAIT(n)  asm volatile("cp.async.wait_group %0;" :: "n"(n) : "memory")

__device__ __forceinline__ void ldm4(uint32_t* r, uint32_t addr) {
    asm volatile("ldmatrix.sync.aligned.m8n8.x4.shared.b16 {%0,%1,%2,%3}, [%4];"
                 : "=r"(r[0]), "=r"(r[1]), "=r"(r[2]), "=r"(r[3]) : "r"(addr));
}
__device__ __forceinline__ void mma_fp16(float* c, const uint32_t* a, const uint32_t* b) {
    asm volatile(
        "mma.sync.aligned.m16n8k16.row.col.f32.f16.f16.f32 "
        "{%0,%1,%2,%3}, {%4,%5,%6,%7}, {%8,%9}, {%0,%1,%2,%3};"
        : "+f"(c[0]), "+f"(c[1]), "+f"(c[2]), "+f"(c[3])
        : "r"(a[0]), "r"(a[1]), "r"(a[2]), "r"(a[3]), "r"(b[0]), "r"(b[1]));
}

// smem tile geometry (both GEMMs): 128 rows x 64 halfs (128 B) + 16 B pad
#define ROW_B   144
#define ARR_SZ  (128 * ROW_B)        // 18432
#define STG_SZ  (3 * ARR_SZ)         // 55296 per stage (3 arrays)
#define OFF_0   0
#define OFF_1   ARR_SZ
#define OFF_2   (2 * ARR_SZ)
#define SMEM_GEMM (2 * STG_SZ)       // 110592

// ---------------------------------------------------------------------------
__global__ __launch_bounds__(256) void k_norm(const float* __restrict__ mask) {
    const int i = blockIdx.x;
    const int j = threadIdx.x;
    __shared__ float colI[S_DIM];
    colI[j] = mask[j * N_DIM + i];
    __syncthreads();
    float acc = 0.0f;
#pragma unroll 8
    for (int s = 0; s < S_DIM; s++) acc += colI[s] * mask[s * N_DIM + j];
    g_rnorm[i * N_DIM + j] = 1.0f / (acc + 1e-3f);
}

__global__ __launch_bounds__(256) void k_wprep(const float* __restrict__ wout) {
    const int z = blockIdx.x;
    for (int k = threadIdx.x; k < 1024; k += 256) {
        const float w = wout[(size_t)k * CZ + z];
        const __half h = __float2half(w);
        g_Wh[z * 1024 + k] = h;
        g_Wl[z * 1024 + k] = __float2half(w - __half2float(h));
    }
}

// ---------------------------------------------------------------------------
// LN + dual projection, batched phases; psum overlays dead xs region (32 KB).
// grid = (n=256, sg=8); 256 threads; rows s = sg*32..+32 at fixed n.
// ---------------------------------------------------------------------------
__global__ __launch_bounds__(256) void k_lnproj(
    const float* __restrict__ m, const float* __restrict__ mask,
    const float* __restrict__ lnw, const float* __restrict__ lnb,
    const float* __restrict__ w1, const float* __restrict__ b1,
    const float* __restrict__ w2, const float* __restrict__ b2)
{
    const int tid  = threadIdx.x;
    const int lane = tid & 31;
    const int wid  = tid >> 5;
    const int n    = blockIdx.x;
    const int sg   = blockIdx.y;

    __shared__ float xs[32 * 256];          // phase A-D: rows; phase E: psum
    __shared__ float mu_s[32], inv_s[32];

    const int c = tid & 63;
    const int g = tid >> 6;
    float4 wreg[16];
#pragma unroll
    for (int k4 = 0; k4 < 16; k4++) {
        const int k = g * 64 + k4 * 4;
        if (c < CH) {
            wreg[k4] = make_float4(w1[k * CH + c], w1[(k + 1) * CH + c],
                                   w1[(k + 2) * CH + c], w1[(k + 3) * CH + c]);
        } else {
            const int cc = c - CH;
            wreg[k4] = make_float4(w2[k * CH + cc], w2[(k + 1) * CH + cc],
                                   w2[(k + 2) * CH + cc], w2[(k + 3) * CH + cc]);
        }
    }
    const float wln = lnw[tid];
    const float bln = lnb[tid];

    // Phase A: load 32 rows (coalesced float4)
#pragma unroll
    for (int l = 0; l < 8; l++) {
        const int idx = tid + 256 * l;
        const int r   = idx >> 6;
        const int c4  = idx & 63;
        const size_t row = (size_t)((sg * 32 + r) * N_DIM + n);
        ((float4*)xs)[r * 64 + c4] = ((const float4*)(m + row * CM))[c4];
    }
    __syncthreads();

    // Phase B: stats, warp w handles rows 4w..4w+3
#pragma unroll
    for (int rr = 0; rr < 4; rr++) {
        const int r = wid * 4 + rr;
        float s1 = 0.f, s2 = 0.f;
#pragma unroll
        for (int q = 0; q < 8; q++) {
            const float x = xs[r * 256 + lane + 32 * q];
            s1 += x; s2 += x * x;
        }
#pragma unroll
        for (int off = 16; off; off >>= 1) {
            s1 += __shfl_xor_sync(0xffffffffu, s1, off);
            s2 += __shfl_xor_sync(0xffffffffu, s2, off);
        }
        if (lane == 0) {
            const float mean = s1 * (1.0f / CM);
            const float var  = s2 * (1.0f / CM) - mean * mean;
            mu_s[r]  = mean;
            inv_s[r] = rsqrtf(var + 1e-5f);
        }
    }
    __syncthreads();

    // Phase C: normalize column tid across all rows (in place)
#pragma unroll 4
    for (int r = 0; r < 32; r++) {
        const float x = xs[r * 256 + tid];
        xs[r * 256 + tid] = (x - mu_s[r]) * inv_s[r] * wln + bln;
    }
    __syncthreads();

    // Phase D: projection partials kept in registers
    float pr[32];
#pragma unroll 2
    for (int r = 0; r < 32; r++) {
        const float4* yp = (const float4*)&xs[r * 256 + g * 64];
        float p = 0.f;
#pragma unroll
        for (int k4 = 0; k4 < 16; k4++) {
            const float4 y = yp[k4];
            const float4 w = wreg[k4];
            p += y.x * w.x + y.y * w.y + y.z * w.z + y.w * w.w;
        }
        pr[r] = p;
    }
    __syncthreads();     // xs reads done -> safe to overwrite with psum

#pragma unroll
    for (int rr = 0; rr < 32; rr++) {
        const int r = (lane + rr) & 31;
        xs[(g * 64 + c) * 32 + r] = pr[r];
    }
    __syncthreads();

    // Phase E: reduce over g, bias, mask, fp16 emit (A split, B plain)
    const int r = tid & 31;
    const size_t row = (size_t)((sg * 32 + r) * N_DIM + n);
    const float msk = mask[row];
#pragma unroll
    for (int l = 0; l < 8; l++) {
        const int cc = (tid >> 5) + 8 * l;      // 0..63
        const float tot = xs[(0 * 64 + cc) * 32 + r] + xs[(1 * 64 + cc) * 32 + r] +
                          xs[(2 * 64 + cc) * 32 + r] + xs[(3 * 64 + cc) * 32 + r];
        const float bias = (cc < CH) ? b1[cc] : b2[cc - CH];
        const float v = (tot + bias) * msk;
        if (cc < CH) {
            const size_t mrow = (size_t)(n * CH + cc) * S_DIM + sg * 32 + r;
            const __half h = __float2half(v);
            g_Ah[mrow] = h;
            g_Al[mrow] = __float2half(v - __half2float(h));
        } else {
            const size_t mrow = (size_t)(n * CH + (cc - CH)) * S_DIM + sg * 32 + r;
            g_B[mrow] = __float2half(v);
        }
    }
}

// ---------------------------------------------------------------------------
// K2: C = (Ah+Al) B^T, 2-pass HMMA. CTA tile 128x128, K=256 in 4 chunks of 64.
// 8 warps as 4(m) x 2(n); warp tile 32(m) x 64(n).
// ---------------------------------------------------------------------------
__global__ __launch_bounds__(256, 2) void k_gemm1() {
    extern __shared__ char smraw[];
    const uint32_t sm0 = smem_u32(smraw);
    const int tid  = threadIdx.x;
    const int wid  = tid >> 5;
    const int lane = tid & 31;
    const int m0 = blockIdx.y * 128;
    const int n0 = blockIdx.x * 128;
    const int wm0 = (wid & 3) * 32;
    const int wn0 = (wid >> 2) * 64;

    const int ar = lane & 15;
    const int ak = (lane >> 4) * 16;
    const int br = (lane & 7) + ((lane >> 4) << 3);
    const int bk = ((lane >> 3) & 1) * 16;
    const uint32_t aoff = (uint32_t)(wm0 + ar) * ROW_B + ak;
    const uint32_t boff = (uint32_t)(wn0 + br) * ROW_B + bk;

    float acc[2][8][4];
#pragma unroll
    for (int t = 0; t < 2; t++)
#pragma unroll
        for (int j = 0; j < 8; j++)
#pragma unroll
            for (int q = 0; q < 4; q++) acc[t][j][q] = 0.f;

    auto stage = [&](int kc, uint32_t sbuf) {
#pragma unroll
        for (int l = 0; l < 4; l++) {
            const int idx = tid + 256 * l;      // 1024: row(128) x seg(8)
            const int row = idx >> 3;
            const int seg = idx & 7;
            const uint32_t d = sbuf + row * ROW_B + seg * 16;
            const size_t sa = (size_t)(m0 + row) * S_DIM + kc * 64 + seg * 8;
            const size_t sb = (size_t)(n0 + row) * S_DIM + kc * 64 + seg * 8;
            cp16(d + OFF_0, g_Ah + sa);
            cp16(d + OFF_1, g_Al + sa);
            cp16(d + OFF_2, g_B  + sb);
        }
        CP_COMMIT();
    };

    stage(0, sm0);
    stage(1, sm0 + STG_SZ);

    for (int kc = 0; kc < 4; kc++) {
        if (kc < 3) { CP_WAIT(1); } else { CP_WAIT(0); }
        __syncthreads();
        const uint32_t sbuf = sm0 + (kc & 1) * STG_SZ;
#pragma unroll
        for (int ks = 0; ks < 4; ks++) {
            uint32_t aH[2][4], aL[2][4], b[4][4];
#pragma unroll
            for (int t = 0; t < 2; t++) {
                const uint32_t a = sbuf + aoff + t * (16 * ROW_B) + ks * 32;
                ldm4(aH[t], a + OFF_0);
                ldm4(aL[t], a + OFF_1);
            }
#pragma unroll
            for (int p = 0; p < 4; p++)
                ldm4(b[p], sbuf + boff + p * (16 * ROW_B) + ks * 32 + OFF_2);
#pragma unroll
            for (int t = 0; t < 2; t++) {
#pragma unroll
                for (int j = 0; j < 8; j++) {
                    const uint32_t* bp = &b[j >> 1][(j & 1) * 2];
                    mma_fp16(acc[t][j], aH[t], bp);
                    mma_fp16(acc[t][j], aL[t], bp);
                }
            }
        }
        __syncthreads();
        if (kc + 2 < 4) stage(kc + 2, sbuf);
    }

    // epilogue: plain fp16 C, packed u32 stores (row-major)
#pragma unroll
    for (int t = 0; t < 2; t++) {
        const int mg = m0 + wm0 + t * 16 + (lane >> 2);
#pragma unroll
        for (int j = 0; j < 8; j++) {
            const int nn = n0 + wn0 + j * 8 + (lane & 3) * 2;
            const float* cc = acc[t][j];
#pragma unroll
            for (int h = 0; h < 2; h++) {
                __half2 hp;
                hp.x = __float2half(cc[h * 2 + 0]);
                hp.y = __float2half(cc[h * 2 + 1]);
                const size_t o = (size_t)(mg + h * 8) * NH + nn;
                *(uint32_t*)(g_C + o) = *(uint32_t*)&hp;
            }
        }
    }
}

// ---------------------------------------------------------------------------
// K3: out[(i,j),z] = (sum_ce C[(i,c),(j,e)] W[ce,z] + b[z]) * rnorm[i,j]
// grid = 512: i = bx>>1, j-half = bx&1. CTA tile 128(j) x 128(z), K=1024 in
// 16 chunks of 64 (= 2 C rows x 32 e, contiguous 64 B segments).
// ---------------------------------------------------------------------------
__global__ __launch_bounds__(256, 2) void k_gemm2(
    const float* __restrict__ bout, float* __restrict__ out)
{
    extern __shared__ char smraw[];
    const uint32_t sm0 = smem_u32(smraw);
    const int tid  = threadIdx.x;
    const int wid  = tid >> 5;
    const int lane = tid & 31;
    const int i  = blockIdx.x >> 1;
    const int jh = blockIdx.x & 1;
    const int wm0 = (wid & 3) * 32;      // j within tile
    const int wn0 = (wid >> 2) * 64;     // z

    const int ar = lane & 15;
    const int ak = (lane >> 4) * 16;
    const int br = (lane & 7) + ((lane >> 4) << 3);
    const int bk = ((lane >> 3) & 1) * 16;
    const uint32_t aoff = (uint32_t)(wm0 + ar) * ROW_B + ak;
    const uint32_t boff = (uint32_t)(wn0 + br) * ROW_B + bk;

    float acc[2][8][4];
#pragma unroll
    for (int t = 0; t < 2; t++)
#pragma unroll
        for (int j = 0; j < 8; j++)
#pragma unroll
            for (int q = 0; q < 4; q++) acc[t][j][q] = 0.f;

    auto stage = [&](int kc, uint32_t sbuf) {
#pragma unroll
        for (int l = 0; l < 4; l++) {
            const int idx = tid + 256 * l;
            const int row = idx >> 3;            // j-row (C) / z-row (W)
            const int seg = idx & 7;             // k-halfs seg*8..+8
            const uint32_t d = sbuf + row * ROW_B + seg * 16;
            // C source: c = kc*2 + (seg>>2), e = (seg&3)*8
            const size_t sc = (size_t)(i * 32 + kc * 2 + (seg >> 2)) * NH +
                              (size_t)(jh * 128 + row) * 32 + (seg & 3) * 8;
            const size_t sw = (size_t)row * 1024 + kc * 64 + seg * 8;
            cp16(d + OFF_0, g_C  + sc);
            cp16(d + OFF_1, g_Wh + sw);
            cp16(d + OFF_2, g_Wl + sw);
        }
        CP_COMMIT();
    };

    stage(0, sm0);
    stage(1, sm0 + STG_SZ);

    for (int kc = 0; kc < 16; kc++) {
        if (kc < 15) { CP_WAIT(1); } else { CP_WAIT(0); }
        __syncthreads();
        const uint32_t sbuf = sm0 + (kc & 1) * STG_SZ;
#pragma unroll
        for (int ks = 0; ks < 4; ks++) {
            uint32_t aC[2][4], bH[4][4], bL[4][4];
#pragma unroll
            for (int t = 0; t < 2; t++)
                ldm4(aC[t], sbuf + aoff + t * (16 * ROW_B) + ks * 32 + OFF_0);
#pragma unroll
            for (int p = 0; p < 4; p++) {
                const uint32_t b = sbuf + boff + p * (16 * ROW_B) + ks * 32;
                ldm4(bH[p], b + OFF_1);
                ldm4(bL[p], b + OFF_2);
            }
#pragma unroll
            for (int t = 0; t < 2; t++) {
#pragma unroll
                for (int j = 0; j < 8; j++) {
                    const uint32_t* bh = &bH[j >> 1][(j & 1) * 2];
                    const uint32_t* bl = &bL[j >> 1][(j & 1) * 2];
                    mma_fp16(acc[t][j], aC[t], bh);
                    mma_fp16(acc[t][j], aC[t], bl);
                }
            }
        }
        __syncthreads();
        if (kc + 2 < 16) stage(kc + 2, sbuf);
    }

    // epilogue: + bias, * rnorm, fp32 stores
#pragma unroll
    for (int t = 0; t < 2; t++) {
        const int jg = jh * 128 + wm0 + t * 16 + (lane >> 2);
        const float rn0 = g_rnorm[i * N_DIM + jg];
        const float rn1 = g_rnorm[i * N_DIM + jg + 8];
#pragma unroll
        for (int j = 0; j < 8; j++) {
            const int z = wn0 + j * 8 + (lane & 3) * 2;
            const float2 bz = *(const float2*)(bout + z);
            const float* cc = acc[t][j];
            float2 o0, o1;
            o0.x = (cc[0] + bz.x) * rn0;  o0.y = (cc[1] + bz.y) * rn0;
            o1.x = (cc[2] + bz.x) * rn1;  o1.y = (cc[3] + bz.y) * rn1;
            *(float2*)(out + (size_t)(i * N_DIM + jg) * CZ + z)     = o0;
            *(float2*)(out + (size_t)(i * N_DIM + jg + 8) * CZ + z) = o1;
        }
    }
}

// ---------------------------------------------------------------------------
extern "C" void kernel_launch(void* const* d_in, const int* in_sizes, int n_in,
                              void* d_out, int out_size)
{
    (void)in_sizes; (void)n_in; (void)out_size;
    const float* m    = (const float*)d_in[0];
    const float* mask = (const float*)d_in[1];
    const float* lnw  = (const float*)d_in[2];
    const float* lnb  = (const float*)d_in[3];
    const float* w1   = (const float*)d_in[4];
    const float* b1   = (const float*)d_in[5];
    const float* w2   = (const float*)d_in[6];
    const float* b2   = (const float*)d_in[7];
    const float* wout = (const float*)d_in[8];
    const float* bout = (const float*)d_in[9];
    float* out = (float*)d_out;

    cudaFuncSetAttribute((const void*)k_gemm1,
                         cudaFuncAttributeMaxDynamicSharedMemorySize, SMEM_GEMM);
    cudaFuncSetAttribute((const void*)k_gemm2,
                         cudaFuncAttributeMaxDynamicSharedMemorySize, SMEM_GEMM);

    k_lnproj<<<dim3(N_DIM, 8), 256>>>(m, mask, lnw, lnb, w1, b1, w2, b2);
    k_wprep<<<CZ, 256>>>(wout);
    k_norm<<<N_DIM, 256>>>(mask);
    k_gemm1<<<dim3(NH / 128, NH / 128), 256, SMEM_GEMM>>>();
    k_gemm2<<<512, 256, SMEM_GEMM>>>(bout, out);
}

// round 12
// speedup vs baseline: 2.8385x; 1.3756x over previous
#include <cuda_runtime.h>
#include <cuda_fp16.h>
#include <cstdint>

// ---------------------------------------------------------------------------
// OuterProductMean: S=256, N=256, c_m=256, c_h=32, c_z=128
//   k_lnproj : LN + dual projection -> A, B plain fp16, K-major [m=8192][s=256]
//   k_wprep  : w_out fp32 [1024][128] -> plain fp16 transposed [z=128][k=1024]
//   k_norm   : g_rnorm[i,j] = 1/(sum_s mask[s,i]mask[s,j] + 1e-3)
//   k_gemm1  : HMMA 1-pass  C[8192x8192] = A B^T (K=256), C plain fp16
//   k_gemm2  : HMMA 1-pass  out = C W + bias, * rnorm
// fp16 error model: 4 independent quantization sources (A,B,C,W) ~2.1e-4 each
// -> ~4.2e-4 total, under the 1e-3 gate with 2.4x margin.
// All PTX sm_80-compatible (mma.sync/ldmatrix/cp.async) -> ok for compute_100.
// ---------------------------------------------------------------------------

#define S_DIM 256
#define N_DIM 256
#define CM    256
#define CH    32
#define CZ    128
#define NH    8192

__device__ __align__(16) __half g_A [(size_t)NH * S_DIM];
__device__ __align__(16) __half g_B [(size_t)NH * S_DIM];
__device__ __align__(16) __half g_C [(size_t)NH * NH];     // 134 MB
__device__ __align__(16) __half g_W [CZ * 1024];
__device__ __align__(16) float g_rnorm[N_DIM * N_DIM];

// ---- PTX helpers -----------------------------------------------------------
__device__ __forceinline__ uint32_t smem_u32(const void* p) {
    uint32_t a;
    asm("{ .reg .u64 t; cvta.to.shared.u64 t, %1; cvt.u32.u64 %0, t; }" : "=r"(a) : "l"(p));
    return a;
}
__device__ __forceinline__ void cp16(uint32_t dst, const void* src) {
    asm volatile("cp.async.cg.shared.global [%0], [%1], 16;" :: "r"(dst), "l"(src));
}
#define CP_COMMIT() asm volatile("cp.async.commit_group;" ::: "memory")
#define CP_WAIT(n)  asm volatile("cp.async.wait_group %0;" :: "n"(n) : "memory")

__device__ __forceinline__ void ldm4(uint32_t* r, uint32_t addr) {
    asm volatile("ldmatrix.sync.aligned.m8n8.x4.shared.b16 {%0,%1,%2,%3}, [%4];"
                 : "=r"(r[0]), "=r"(r[1]), "=r"(r[2]), "=r"(r[3]) : "r"(addr));
}
__device__ __forceinline__ void mma_fp16(float* c, const uint32_t* a, const uint32_t* b) {
    asm volatile(
        "mma.sync.aligned.m16n8k16.row.col.f32.f16.f16.f32 "
        "{%0,%1,%2,%3}, {%4,%5,%6,%7}, {%8,%9}, {%0,%1,%2,%3};"
        : "+f"(c[0]), "+f"(c[1]), "+f"(c[2]), "+f"(c[3])
        : "r"(a[0]), "r"(a[1]), "r"(a[2]), "r"(a[3]), "r"(b[0]), "r"(b[1]));
}

// smem tile geometry (both GEMMs): 128 rows x 64 halfs (128 B) + 16 B pad
#define ROW_B   144
#define ARR_SZ  (128 * ROW_B)        // 18432
#define STG_SZ  (2 * ARR_SZ)         // 36864 per stage (2 arrays)
#define OFF_0   0
#define OFF_1   ARR_SZ
#define NSTG    3
#define SMEM_GEMM (NSTG * STG_SZ)    // 110592 -> 2 CTAs/SM

// ---------------------------------------------------------------------------
__global__ __launch_bounds__(256) void k_norm(const float* __restrict__ mask) {
    const int i = blockIdx.x;
    const int j = threadIdx.x;
    __shared__ float colI[S_DIM];
    colI[j] = mask[j * N_DIM + i];
    __syncthreads();
    float acc = 0.0f;
#pragma unroll 8
    for (int s = 0; s < S_DIM; s++) acc += colI[s] * mask[s * N_DIM + j];
    g_rnorm[i * N_DIM + j] = 1.0f / (acc + 1e-3f);
}

__global__ __launch_bounds__(256) void k_wprep(const float* __restrict__ wout) {
    const int z = blockIdx.x;
    for (int k = threadIdx.x; k < 1024; k += 256)
        g_W[z * 1024 + k] = __float2half(wout[(size_t)k * CZ + z]);
}

// ---------------------------------------------------------------------------
// LN + dual projection, batched phases; psum overlays dead xs region (32 KB).
// grid = (n=256, sg=8); 256 threads; rows s = sg*32..+32 at fixed n.
// ---------------------------------------------------------------------------
__global__ __launch_bounds__(256) void k_lnproj(
    const float* __restrict__ m, const float* __restrict__ mask,
    const float* __restrict__ lnw, const float* __restrict__ lnb,
    const float* __restrict__ w1, const float* __restrict__ b1,
    const float* __restrict__ w2, const float* __restrict__ b2)
{
    const int tid  = threadIdx.x;
    const int lane = tid & 31;
    const int wid  = tid >> 5;
    const int n    = blockIdx.x;
    const int sg   = blockIdx.y;

    __shared__ float xs[32 * 256];          // phase A-D: rows; phase E: psum
    __shared__ float mu_s[32], inv_s[32];

    const int c = tid & 63;
    const int g = tid >> 6;
    float4 wreg[16];
#pragma unroll
    for (int k4 = 0; k4 < 16; k4++) {
        const int k = g * 64 + k4 * 4;
        if (c < CH) {
            wreg[k4] = make_float4(w1[k * CH + c], w1[(k + 1) * CH + c],
                                   w1[(k + 2) * CH + c], w1[(k + 3) * CH + c]);
        } else {
            const int cc = c - CH;
            wreg[k4] = make_float4(w2[k * CH + cc], w2[(k + 1) * CH + cc],
                                   w2[(k + 2) * CH + cc], w2[(k + 3) * CH + cc]);
        }
    }
    const float wln = lnw[tid];
    const float bln = lnb[tid];

    // Phase A: load 32 rows (coalesced float4)
#pragma unroll
    for (int l = 0; l < 8; l++) {
        const int idx = tid + 256 * l;
        const int r   = idx >> 6;
        const int c4  = idx & 63;
        const size_t row = (size_t)((sg * 32 + r) * N_DIM + n);
        ((float4*)xs)[r * 64 + c4] = ((const float4*)(m + row * CM))[c4];
    }
    __syncthreads();

    // Phase B: stats, warp w handles rows 4w..4w+3
#pragma unroll
    for (int rr = 0; rr < 4; rr++) {
        const int r = wid * 4 + rr;
        float s1 = 0.f, s2 = 0.f;
#pragma unroll
        for (int q = 0; q < 8; q++) {
            const float x = xs[r * 256 + lane + 32 * q];
            s1 += x; s2 += x * x;
        }
#pragma unroll
        for (int off = 16; off; off >>= 1) {
            s1 += __shfl_xor_sync(0xffffffffu, s1, off);
            s2 += __shfl_xor_sync(0xffffffffu, s2, off);
        }
        if (lane == 0) {
            const float mean = s1 * (1.0f / CM);
            const float var  = s2 * (1.0f / CM) - mean * mean;
            mu_s[r]  = mean;
            inv_s[r] = rsqrtf(var + 1e-5f);
        }
    }
    __syncthreads();

    // Phase C: normalize column tid across all rows (in place)
#pragma unroll 4
    for (int r = 0; r < 32; r++) {
        const float x = xs[r * 256 + tid];
        xs[r * 256 + tid] = (x - mu_s[r]) * inv_s[r] * wln + bln;
    }
    __syncthreads();

    // Phase D: projection partials kept in registers
    float pr[32];
#pragma unroll 2
    for (int r = 0; r < 32; r++) {
        const float4* yp = (const float4*)&xs[r * 256 + g * 64];
        float p = 0.f;
#pragma unroll
        for (int k4 = 0; k4 < 16; k4++) {
            const float4 y = yp[k4];
            const float4 w = wreg[k4];
            p += y.x * w.x + y.y * w.y + y.z * w.z + y.w * w.w;
        }
        pr[r] = p;
    }
    __syncthreads();     // xs reads done -> safe to overwrite with psum

#pragma unroll
    for (int rr = 0; rr < 32; rr++) {
        const int r = (lane + rr) & 31;
        xs[(g * 64 + c) * 32 + r] = pr[r];
    }
    __syncthreads();

    // Phase E: reduce over g, bias, mask, plain fp16 emit
    const int r = tid & 31;
    const size_t row = (size_t)((sg * 32 + r) * N_DIM + n);
    const float msk = mask[row];
#pragma unroll
    for (int l = 0; l < 8; l++) {
        const int cc = (tid >> 5) + 8 * l;      // 0..63
        const float tot = xs[(0 * 64 + cc) * 32 + r] + xs[(1 * 64 + cc) * 32 + r] +
                          xs[(2 * 64 + cc) * 32 + r] + xs[(3 * 64 + cc) * 32 + r];
        const float bias = (cc < CH) ? b1[cc] : b2[cc - CH];
        const float v = (tot + bias) * msk;
        if (cc < CH) {
            const size_t mrow = (size_t)(n * CH + cc) * S_DIM + sg * 32 + r;
            g_A[mrow] = __float2half(v);
        } else {
            const size_t mrow = (size_t)(n * CH + (cc - CH)) * S_DIM + sg * 32 + r;
            g_B[mrow] = __float2half(v);
        }
    }
}

// ---------------------------------------------------------------------------
// K2: C = A B^T, 1-pass HMMA. CTA tile 128x128, K=256 in 4 chunks of 64,
// 3-stage ring. 8 warps as 4(m) x 2(n); warp tile 32(m) x 64(n).
// ---------------------------------------------------------------------------
__global__ __launch_bounds__(256, 2) void k_gemm1() {
    extern __shared__ char smraw[];
    const uint32_t sm0 = smem_u32(smraw);
    const int tid  = threadIdx.x;
    const int wid  = tid >> 5;
    const int lane = tid & 31;
    const int m0 = blockIdx.y * 128;
    const int n0 = blockIdx.x * 128;
    const int wm0 = (wid & 3) * 32;
    const int wn0 = (wid >> 2) * 64;

    const int ar = lane & 15;
    const int ak = (lane >> 4) * 16;
    const int br = (lane & 7) + ((lane >> 4) << 3);
    const int bk = ((lane >> 3) & 1) * 16;
    const uint32_t aoff = (uint32_t)(wm0 + ar) * ROW_B + ak;
    const uint32_t boff = (uint32_t)(wn0 + br) * ROW_B + bk;

    float acc[2][8][4];
#pragma unroll
    for (int t = 0; t < 2; t++)
#pragma unroll
        for (int j = 0; j < 8; j++)
#pragma unroll
            for (int q = 0; q < 4; q++) acc[t][j][q] = 0.f;

    auto stage = [&](int kc, uint32_t sbuf) {
#pragma unroll
        for (int l = 0; l < 4; l++) {
            const int idx = tid + 256 * l;      // 1024: row(128) x seg(8)
            const int row = idx >> 3;
            const int seg = idx & 7;
            const uint32_t d = sbuf + row * ROW_B + seg * 16;
            const size_t sa = (size_t)(m0 + row) * S_DIM + kc * 64 + seg * 8;
            const size_t sb = (size_t)(n0 + row) * S_DIM + kc * 64 + seg * 8;
            cp16(d + OFF_0, g_A + sa);
            cp16(d + OFF_1, g_B + sb);
        }
        CP_COMMIT();
    };

    stage(0, sm0);
    stage(1, sm0 + STG_SZ);
    stage(2, sm0 + 2 * STG_SZ);

#pragma unroll
    for (int kc = 0; kc < 4; kc++) {
        if (kc <= 1)      { CP_WAIT(2); }
        else if (kc == 2) { CP_WAIT(1); }
        else              { CP_WAIT(0); }
        __syncthreads();
        const uint32_t sbuf = sm0 + (kc % 3) * STG_SZ;
#pragma unroll
        for (int ks = 0; ks < 4; ks++) {
            uint32_t a[2][4], b[4][4];
#pragma unroll
            for (int t = 0; t < 2; t++)
                ldm4(a[t], sbuf + aoff + t * (16 * ROW_B) + ks * 32 + OFF_0);
#pragma unroll
            for (int p = 0; p < 4; p++)
                ldm4(b[p], sbuf + boff + p * (16 * ROW_B) + ks * 32 + OFF_1);
#pragma unroll
            for (int t = 0; t < 2; t++) {
#pragma unroll
                for (int j = 0; j < 8; j++)
                    mma_fp16(acc[t][j], a[t], &b[j >> 1][(j & 1) * 2]);
            }
        }
        __syncthreads();
        if (kc + 3 < 4) stage(kc + 3, sbuf);
    }

    // epilogue: plain fp16 C, packed u32 stores (row-major)
#pragma unroll
    for (int t = 0; t < 2; t++) {
        const int mg = m0 + wm0 + t * 16 + (lane >> 2);
#pragma unroll
        for (int j = 0; j < 8; j++) {
            const int nn = n0 + wn0 + j * 8 + (lane & 3) * 2;
            const float* cc = acc[t][j];
#pragma unroll
            for (int h = 0; h < 2; h++) {
                __half2 hp;
                hp.x = __float2half(cc[h * 2 + 0]);
                hp.y = __float2half(cc[h * 2 + 1]);
                const size_t o = (size_t)(mg + h * 8) * NH + nn;
                *(uint32_t*)(g_C + o) = *(uint32_t*)&hp;
            }
        }
    }
}

// ---------------------------------------------------------------------------
// K3: out[(i,j),z] = (sum_ce C[(i,c),(j,e)] W[ce,z] + b[z]) * rnorm[i,j]
// grid = 512: i = bx>>1, j-half = bx&1. CTA tile 128(j) x 128(z), K=1024 in
// 16 chunks of 64 (= 2 C rows x 32 e, contiguous 64 B segments), 3-stage ring.
// ---------------------------------------------------------------------------
__global__ __launch_bounds__(256, 2) void k_gemm2(
    const float* __restrict__ bout, float* __restrict__ out)
{
    extern __shared__ char smraw[];
    const uint32_t sm0 = smem_u32(smraw);
    const int tid  = threadIdx.x;
    const int wid  = tid >> 5;
    const int lane = tid & 31;
    const int i  = blockIdx.x >> 1;
    const int jh = blockIdx.x & 1;
    const int wm0 = (wid & 3) * 32;      // j within tile
    const int wn0 = (wid >> 2) * 64;     // z

    const int ar = lane & 15;
    const int ak = (lane >> 4) * 16;
    const int br = (lane & 7) + ((lane >> 4) << 3);
    const int bk = ((lane >> 3) & 1) * 16;
    const uint32_t aoff = (uint32_t)(wm0 + ar) * ROW_B + ak;
    const uint32_t boff = (uint32_t)(wn0 + br) * ROW_B + bk;

    float acc[2][8][4];
#pragma unroll
    for (int t = 0; t < 2; t++)
#pragma unroll
        for (int j = 0; j < 8; j++)
#pragma unroll
            for (int q = 0; q < 4; q++) acc[t][j][q] = 0.f;

    auto stage = [&](int kc, uint32_t sbuf) {
#pragma unroll
        for (int l = 0; l < 4; l++) {
            const int idx = tid + 256 * l;
            const int row = idx >> 3;            // j-row (C) / z-row (W)
            const int seg = idx & 7;             // k-halfs seg*8..+8
            const uint32_t d = sbuf + row * ROW_B + seg * 16;
            // C source: c = kc*2 + (seg>>2), e = (seg&3)*8
            const size_t sc = (size_t)(i * 32 + kc * 2 + (seg >> 2)) * NH +
                              (size_t)(jh * 128 + row) * 32 + (seg & 3) * 8;
            const size_t sw = (size_t)row * 1024 + kc * 64 + seg * 8;
            cp16(d + OFF_0, g_C + sc);
            cp16(d + OFF_1, g_W + sw);
        }
        CP_COMMIT();
    };

    stage(0, sm0);
    stage(1, sm0 + STG_SZ);
    stage(2, sm0 + 2 * STG_SZ);

    for (int kc = 0; kc < 16; kc++) {
        if (kc < 14)       { CP_WAIT(2); }
        else if (kc == 14) { CP_WAIT(1); }
        else               { CP_WAIT(0); }
        __syncthreads();
        const uint32_t sbuf = sm0 + (kc % 3) * STG_SZ;
#pragma unroll
        for (int ks = 0; ks < 4; ks++) {
            uint32_t a[2][4], b[4][4];
#pragma unroll
            for (int t = 0; t < 2; t++)
                ldm4(a[t], sbuf + aoff + t * (16 * ROW_B) + ks * 32 + OFF_0);
#pragma unroll
            for (int p = 0; p < 4; p++)
                ldm4(b[p], sbuf + boff + p * (16 * ROW_B) + ks * 32 + OFF_1);
#pragma unroll
            for (int t = 0; t < 2; t++) {
#pragma unroll
                for (int j = 0; j < 8; j++)
                    mma_fp16(acc[t][j], a[t], &b[j >> 1][(j & 1) * 2]);
            }
        }
        __syncthreads();
        if (kc + 3 < 16) stage(kc + 3, sbuf);
    }

    // epilogue: + bias, * rnorm, fp32 stores
#pragma unroll
    for (int t = 0; t < 2; t++) {
        const int jg = jh * 128 + wm0 + t * 16 + (lane >> 2);
        const float rn0 = g_rnorm[i * N_DIM + jg];
        const float rn1 = g_rnorm[i * N_DIM + jg + 8];
#pragma unroll
        for (int j = 0; j < 8; j++) {
            const int z = wn0 + j * 8 + (lane & 3) * 2;
            const float2 bz = *(const float2*)(bout + z);
            const float* cc = acc[t][j];
            float2 o0, o1;
            o0.x = (cc[0] + bz.x) * rn0;  o0.y = (cc[1] + bz.y) * rn0;
            o1.x = (cc[2] + bz.x) * rn1;  o1.y = (cc[3] + bz.y) * rn1;
            *(float2*)(out + (size_t)(i * N_DIM + jg) * CZ + z)     = o0;
            *(float2*)(out + (size_t)(i * N_DIM + jg + 8) * CZ + z) = o1;
        }
    }
}

// ---------------------------------------------------------------------------
extern "C" void kernel_launch(void* const* d_in, const int* in_sizes, int n_in,
                              void* d_out, int out_size)
{
    (void)in_sizes; (void)n_in; (void)out_size;
    const float* m    = (const float*)d_in[0];
    const float* mask = (const float*)d_in[1];
    const float* lnw  = (const float*)d_in[2];
    const float* lnb  = (const float*)d_in[3];
    const float* w1   = (const float*)d_in[4];
    const float* b1   = (const float*)d_in[5];
    const float* w2   = (const float*)d_in[6];
    const float* b2   = (const float*)d_in[7];
    const float* wout = (const float*)d_in[8];
    const float* bout = (const float*)d_in[9];
    float* out = (float*)d_out;

    cudaFuncSetAttribute((const void*)k_gemm1,
                         cudaFuncAttributeMaxDynamicSharedMemorySize, SMEM_GEMM);
    cudaFuncSetAttribute((const void*)k_gemm2,
                         cudaFuncAttributeMaxDynamicSharedMemorySize, SMEM_GEMM);

    k_lnproj<<<dim3(N_DIM, 8), 256>>>(m, mask, lnw, lnb, w1, b1, w2, b2);
    k_wprep<<<CZ, 256>>>(wout);
    k_norm<<<N_DIM, 256>>>(mask);
    k_gemm1<<<dim3(NH / 128, NH / 128), 256, SMEM_GEMM>>>();
    k_gemm2<<<512, 256, SMEM_GEMM>>>(bout, out);
}